// round 3
// baseline (speedup 1.0000x reference)
#include <cuda_runtime.h>

#define BS    16
#define CCH   256
#define NPIX  16384
#define TOPK  12
#define TPB   256
#define ACH   16         // phaseA chunks per batch

// Device-global scratch (no allocations allowed anywhere)
__device__ signed char g_mask[BS * NPIX];          // bit0 = fg mask, bit1 = bg mask
__device__ int         g_cntp[2 * BS * ACH];       // per-chunk partial counts [side][b][chunk]
__device__ int         g_anomp[BS * ACH];          // per-chunk anomaly counts (mask not complementary)
__device__ int         g_idx[2 * BS * TOPK];       // fallback top-12 indices (valid only if cnt==0)

// ---------------------------------------------------------------------------
// Phase A: softmax -> masks + partial counts. grid (ACH, BS), 256 thr.
// Each block: NPIX/ACH = 1024 pixels = 256 float4 per channel = 1 iter.
// Single-exp trick: with max-subtraction, exp(0)=1 exactly, so only one expf.
// ---------------------------------------------------------------------------
__device__ __forceinline__ signed char mask_of(float a0, float a1,
                                               float tf, float tb,
                                               int& lf, int& lb, int& la) {
    // exp(a0-m), exp(a1-m) with m = max: the max one is exp(0) == 1.0f exactly
    float d  = fminf(a0, a1) - fmaxf(a0, a1);
    float e  = expf(d);
    float e0 = (a0 < a1) ? e : 1.0f;
    float e1 = (a0 < a1) ? 1.0f : e;
    float den = e0 + e1;
    float pf = e1 / den;
    float pb = e0 / den;
    int s = 0;
    if (pf > tf) { s |= 1; lf++; }
    if (pb > tb) { s |= 2; lb++; }
    if (s == 0 || s == 3) la++;    // not exactly complementary
    return (signed char)s;
}

__global__ void ssp_phaseA(const float* __restrict__ logits,
                           const float* __restrict__ tau_p) {
    int chunk = blockIdx.x, b = blockIdx.y, t = threadIdx.x;
    float tau = tau_p[0];
    float tf  = 1.0f / (1.0f + expf(-tau));
    float tb  = 1.0f - tf;

    const int pix0 = chunk * (NPIX / ACH);
    const float4* o0 = (const float4*)(logits + (size_t)b * 2 * NPIX + pix0);
    const float4* o1 = (const float4*)(logits + (size_t)b * 2 * NPIX + NPIX + pix0);
    char4* mp = (char4*)(g_mask + (size_t)b * NPIX + pix0);

    int lf = 0, lb = 0, la = 0;
    {
        float4 a0 = o0[t], a1 = o1[t];
        char4 m;
        m.x = mask_of(a0.x, a1.x, tf, tb, lf, lb, la);
        m.y = mask_of(a0.y, a1.y, tf, tb, lf, lb, la);
        m.z = mask_of(a0.z, a1.z, tf, tb, lf, lb, la);
        m.w = mask_of(a0.w, a1.w, tf, tb, lf, lb, la);
        mp[t] = m;
    }
    __shared__ int scf[TPB / 32], scb[TPB / 32], sca[TPB / 32];
    #pragma unroll
    for (int off = 16; off; off >>= 1) {
        lf += __shfl_down_sync(0xffffffffu, lf, off);
        lb += __shfl_down_sync(0xffffffffu, lb, off);
        la += __shfl_down_sync(0xffffffffu, la, off);
    }
    if ((t & 31) == 0) { scf[t >> 5] = lf; scb[t >> 5] = lb; sca[t >> 5] = la; }
    __syncthreads();
    if (t == 0) {
        int cf = 0, cb = 0, ca = 0;
        #pragma unroll
        for (int w = 0; w < TPB / 32; w++) { cf += scf[w]; cb += scb[w]; ca += sca[w]; }
        g_cntp[(0 * BS + b) * ACH + chunk] = cf;
        g_cntp[(1 * BS + b) * ACH + chunk] = cb;
        g_anomp[b * ACH + chunk]           = ca;
    }
}

__device__ __forceinline__ int total_cnt(int side, int b) {
    int c = 0;
    #pragma unroll
    for (int k = 0; k < ACH; k++) c += g_cntp[(side * BS + b) * ACH + k];
    return c;
}
__device__ __forceinline__ int total_anom(int b) {
    int c = 0;
    #pragma unroll
    for (int k = 0; k < ACH; k++) c += g_anomp[b * ACH + k];
    return c;
}

// ---------------------------------------------------------------------------
// Top-k fallback: grid 32 = (b, side). Expensive path runs ONLY if cnt==0.
// ---------------------------------------------------------------------------
__global__ void ssp_topk(const float* __restrict__ logits) {
    int b = blockIdx.x & (BS - 1);
    int side = blockIdx.x >> 4;            // 0 = fg, 1 = bg
    if (total_cnt(side, b) > 0) return;    // common path: no work

    int t = threadIdx.x;
    __shared__ float sv[TPB];
    __shared__ int   si[TPB];
    __shared__ int   ch[TOPK];
    const float* o0 = logits + (size_t)b * 2 * NPIX;
    const float* o1 = o0 + NPIX;

    for (int k = 0; k < TOPK; k++) {
        float best = -3.402823466e38f;
        int   bidx = NPIX;
        for (int i = t; i < NPIX; i += TPB) {
            bool excl = false;
            #pragma unroll
            for (int j = 0; j < TOPK; j++)
                if (j < k) excl |= (i == ch[j]);
            if (!excl) {
                float a0 = o0[i], a1 = o1[i];
                float mx = fmaxf(a0, a1);
                float e0 = expf(a0 - mx), e1 = expf(a1 - mx);
                float p = (side == 0) ? e1 / (e0 + e1) : e0 / (e0 + e1);
                if (p > best) { best = p; bidx = i; }
            }
        }
        sv[t] = best; si[t] = bidx;
        __syncthreads();
        for (int off = TPB / 2; off > 0; off >>= 1) {
            if (t < off) {
                float v2 = sv[t + off]; int i2 = si[t + off];
                if (v2 > sv[t] || (v2 == sv[t] && i2 < si[t])) { sv[t] = v2; si[t] = i2; }
            }
            __syncthreads();
        }
        if (t == 0) ch[k] = si[0];
        __syncthreads();
    }
    if (t < TOPK) g_idx[(side * BS + b) * TOPK + t] = ch[t];
}

// ---------------------------------------------------------------------------
// Phase B: streaming masked reduction. One block per (b,c) row.
// Fast path (no mask anomalies): accumulate total + fg only; bg = total - fg.
// ---------------------------------------------------------------------------
__global__ void ssp_phaseB(const float* __restrict__ feat,
                           float* __restrict__ res) {
    int c = blockIdx.x, b = blockIdx.y, t = threadIdx.x;
    size_t rowoff = ((size_t)b * CCH + c) * (size_t)NPIX;
    const float4* row = (const float4*)(feat + rowoff);

    __shared__ float wsf[8], wsb[8];
    __shared__ float tkv[2 * TOPK];
    __shared__ int   scnt[3];          // cnt_fg, cnt_bg, anomaly
    if (t < 2) scnt[t] = total_cnt(t, b);
    if (t == 2) scnt[2] = total_anom(b);
    __syncthreads();

    float sf = 0.0f, sb = 0.0f;
    if (scnt[2] == 0) {
        // ---- fast path: total + fg-masked ----
        const uchar4* sp = (const uchar4*)(g_mask + (size_t)b * NPIX);
        float st = 0.0f;
        #pragma unroll
        for (int it = 0; it < NPIX / 4 / TPB; ++it) {   // 16 x LDG.128 streaming
            int i = t + it * TPB;
            float4 v = __ldcs(&row[i]);
            uchar4 m = sp[i];
            st += (v.x + v.y) + (v.z + v.w);
            if (m.x & 1) sf += v.x;
            if (m.y & 1) sf += v.y;
            if (m.z & 1) sf += v.z;
            if (m.w & 1) sf += v.w;
        }
        sb = st;   // carries per-thread total; bg derived after block reduce
        #pragma unroll
        for (int off = 16; off; off >>= 1) {
            sf += __shfl_down_sync(0xffffffffu, sf, off);
            sb += __shfl_down_sync(0xffffffffu, sb, off);
        }
        if ((t & 31) == 0) { wsf[t >> 5] = sf; wsb[t >> 5] = sb; }
    } else {
        // ---- general path: dual-masked ----
        const uchar4* sp = (const uchar4*)(g_mask + (size_t)b * NPIX);
        #pragma unroll
        for (int it = 0; it < NPIX / 4 / TPB; ++it) {
            int i = t + it * TPB;
            float4 v = __ldcs(&row[i]);
            uchar4 m = sp[i];
            if (m.x & 1) sf += v.x;  if (m.x & 2) sb += v.x;
            if (m.y & 1) sf += v.y;  if (m.y & 2) sb += v.y;
            if (m.z & 1) sf += v.z;  if (m.z & 2) sb += v.z;
            if (m.w & 1) sf += v.w;  if (m.w & 2) sb += v.w;
        }
        #pragma unroll
        for (int off = 16; off; off >>= 1) {
            sf += __shfl_down_sync(0xffffffffu, sf, off);
            sb += __shfl_down_sync(0xffffffffu, sb, off);
        }
        if ((t & 31) == 0) { wsf[t >> 5] = sf; wsb[t >> 5] = sb; }
    }

    // fallback gather only when a count is zero (indices undefined otherwise)
    if (t < 2 * TOPK) {
        int side = t / TOPK, k = t % TOPK;
        float v = 0.0f;
        if (scnt[side] == 0) {
            int idx = g_idx[(side * BS + b) * TOPK + k];
            v = feat[rowoff + (size_t)idx];
        }
        tkv[t] = v;
    }
    __syncthreads();

    if (t == 0) {
        float SF = 0.0f, S2 = 0.0f;
        #pragma unroll
        for (int w = 0; w < 8; w++) { SF += wsf[w]; S2 += wsb[w]; }
        float SB = (scnt[2] == 0) ? (S2 - SF) : S2;   // fast path: S2 = total
        float TF = 0.0f, TB = 0.0f;
        #pragma unroll
        for (int k = 0; k < TOPK; k++) { TF += tkv[k]; TB += tkv[TOPK + k]; }
        int cf = scnt[0], cb = scnt[1];
        float mf = (cf > 0) ? SF / (float)cf : TF / (float)TOPK;
        float mb = (cb > 0) ? SB / (float)cb : TB / (float)TOPK;
        res[b * CCH + c]            = mf;   // fg_proto
        res[BS * CCH + b * CCH + c] = mb;   // bg_proto
    }
}

extern "C" void kernel_launch(void* const* d_in, const int* in_sizes, int n_in,
                              void* d_out, int out_size) {
    const float* feat   = (const float*)d_in[0];   // feature_q (16,256,128,128)
    const float* logits = (const float*)d_in[1];   // out       (16,2,128,128)
    const float* tau    = (const float*)d_in[2];   // tau scalar
    float* res = (float*)d_out;                    // [fg(16*256) | bg(16*256)]

    ssp_phaseA<<<dim3(ACH, BS), TPB>>>(logits, tau);
    ssp_topk<<<2 * BS, TPB>>>(logits);
    ssp_phaseB<<<dim3(CCH, BS), TPB>>>(feat, res);
}